// round 1
// baseline (speedup 1.0000x reference)
#include <cuda_runtime.h>

// Problem constants
#define EDIM   1024
#define MSLOTS 256
#define NROWS  32768   // 8 * 4096

// Scratch (no allocations allowed -> __device__ globals)
__device__ float g_P[MSLOTS * EDIM];                 // P = M @ Wq         [256,1024]
__device__ float g_R[MSLOTS * EDIM];                 // R = M @ Wo^T       [256,1024]
__device__ float g_s0[MSLOTS];                       // s0 = M @ bq        [256]
__device__ float g_w[(size_t)NROWS * MSLOTS];        // softmax weights    [32768,256]

// ---------------------------------------------------------------------------
// Precompute P (mode 0) and R (mode 1): C[m,n] = sum_k M[m,k] * B[k,n]
//   mode 0: B[k,n] = Wq[k*E + n]        (P = M @ Wq)
//   mode 1: B[k,n] = Wo[n*E + k]        (R = M @ Wo^T)
// Tile 64x64x32, 256 threads, 4x4 micro-tile.
// ---------------------------------------------------------------------------
__global__ __launch_bounds__(256) void precompute_kernel(
    const float* __restrict__ Mb, const float* __restrict__ Wq,
    const float* __restrict__ Wo)
{
    constexpr int BM = 64, BN = 64, BK = 32;
    __shared__ float As[BK][BM];
    __shared__ float Bs[BK][BN];
    const int mode = blockIdx.z;
    const int m0 = blockIdx.y * BM;
    const int n0 = blockIdx.x * BN;
    const int tid = threadIdx.x;
    const int tm = tid >> 4, tn = tid & 15;
    float acc[4][4] = {};

    for (int kb = 0; kb < EDIM; kb += BK) {
        // A tile: M rows m0..m0+63, k = kb..kb+31 (transpose into As[k][row])
        {
            int r = tid >> 2, k0 = (tid & 3) * 8;
            float4 v0 = *(const float4*)(Mb + (m0 + r) * EDIM + kb + k0);
            float4 v1 = *(const float4*)(Mb + (m0 + r) * EDIM + kb + k0 + 4);
            As[k0+0][r] = v0.x; As[k0+1][r] = v0.y; As[k0+2][r] = v0.z; As[k0+3][r] = v0.w;
            As[k0+4][r] = v1.x; As[k0+5][r] = v1.y; As[k0+6][r] = v1.z; As[k0+7][r] = v1.w;
        }
        if (mode == 0) {
            // Wq: rows = k (contiguous n) -> direct copy
            int k = tid >> 3, nq = (tid & 7) * 8;
            float4 v0 = *(const float4*)(Wq + (size_t)(kb + k) * EDIM + n0 + nq);
            float4 v1 = *(const float4*)(Wq + (size_t)(kb + k) * EDIM + n0 + nq + 4);
            *(float4*)&Bs[k][nq]     = v0;
            *(float4*)&Bs[k][nq + 4] = v1;
        } else {
            // Wo: B[k,n] = Wo[n*E + k] -> load along k, transpose into Bs[k][n]
            int n = tid >> 2, k0 = (tid & 3) * 8;
            float4 v0 = *(const float4*)(Wo + (size_t)(n0 + n) * EDIM + kb + k0);
            float4 v1 = *(const float4*)(Wo + (size_t)(n0 + n) * EDIM + kb + k0 + 4);
            Bs[k0+0][n] = v0.x; Bs[k0+1][n] = v0.y; Bs[k0+2][n] = v0.z; Bs[k0+3][n] = v0.w;
            Bs[k0+4][n] = v1.x; Bs[k0+5][n] = v1.y; Bs[k0+6][n] = v1.z; Bs[k0+7][n] = v1.w;
        }
        __syncthreads();
        #pragma unroll
        for (int k = 0; k < BK; k++) {
            float a[4], b[4];
            *(float4*)a = *(const float4*)&As[k][tm * 4];
            *(float4*)b = *(const float4*)&Bs[k][tn * 4];
            #pragma unroll
            for (int i = 0; i < 4; i++)
                #pragma unroll
                for (int j = 0; j < 4; j++)
                    acc[i][j] = fmaf(a[i], b[j], acc[i][j]);
        }
        __syncthreads();
    }
    float* C = mode ? g_R : g_P;
    #pragma unroll
    for (int i = 0; i < 4; i++) {
        int m = m0 + tm * 4 + i;
        *(float4*)(C + (size_t)m * EDIM + n0 + tn * 4) =
            make_float4(acc[i][0], acc[i][1], acc[i][2], acc[i][3]);
    }
}

// ---------------------------------------------------------------------------
// s0[m] = sum_e bq[e] * M[m,e].  One warp per slot.
// ---------------------------------------------------------------------------
__global__ void s0_kernel(const float* __restrict__ Mb, const float* __restrict__ bq)
{
    int m = blockIdx.x;
    int lane = threadIdx.x;
    float s = 0.f;
    #pragma unroll
    for (int c = 0; c < 8; c++) {
        int e = lane * 4 + c * 128;
        float4 mv = *(const float4*)(Mb + (size_t)m * EDIM + e);
        float4 bv = *(const float4*)(bq + e);
        s += mv.x * bv.x + mv.y * bv.y + mv.z * bv.z + mv.w * bv.w;
    }
    #pragma unroll
    for (int o = 16; o; o >>= 1) s += __shfl_xor_sync(0xffffffffu, s, o);
    if (lane == 0) g_s0[m] = s;
}

// ---------------------------------------------------------------------------
// scores + softmax fused: per CTA, 64 rows x all 256 slots, K=1024.
// scores[r,m] = sum_e x[r,e]*P[m,e] + s0[m]; w = softmax over m.
// 256 threads, 8x8 micro-tile; warp tm owns rows tm*8..tm*8+7 and the full
// 256-slot extent across its 32 lanes -> softmax via warp shuffles.
// ---------------------------------------------------------------------------
__global__ __launch_bounds__(256) void scores_kernel(const float* __restrict__ x)
{
    constexpr int BM = 64, BK = 32;
    __shared__ float Xs[BK][BM];       // 8 KB
    __shared__ float Ps[BK][MSLOTS];   // 32 KB
    const int row0 = blockIdx.x * BM;
    const int tid = threadIdx.x;
    const int tm = tid >> 5, tn = tid & 31;
    float acc[8][8] = {};

    for (int kb = 0; kb < EDIM; kb += BK) {
        {   // x tile: 64 rows x 32 k, transpose into Xs[k][row]
            int r = tid >> 2, k0 = (tid & 3) * 8;
            const float* xp = x + (size_t)(row0 + r) * EDIM + kb + k0;
            float4 v0 = *(const float4*)xp;
            float4 v1 = *(const float4*)(xp + 4);
            Xs[k0+0][r] = v0.x; Xs[k0+1][r] = v0.y; Xs[k0+2][r] = v0.z; Xs[k0+3][r] = v0.w;
            Xs[k0+4][r] = v1.x; Xs[k0+5][r] = v1.y; Xs[k0+6][r] = v1.z; Xs[k0+7][r] = v1.w;
        }
        {   // P tile: 256 m x 32 k, coalesced (8 threads per row), transpose
            int kq = (tid & 7) * 4;
            int mbase = tid >> 3;   // 0..31
            #pragma unroll
            for (int mm = 0; mm < MSLOTS; mm += 32) {
                int m = mbase + mm;
                float4 v = *(const float4*)(g_P + (size_t)m * EDIM + kb + kq);
                Ps[kq+0][m] = v.x; Ps[kq+1][m] = v.y; Ps[kq+2][m] = v.z; Ps[kq+3][m] = v.w;
            }
        }
        __syncthreads();
        #pragma unroll
        for (int k = 0; k < BK; k++) {
            float a[8], b[8];
            *(float4*)&a[0] = *(const float4*)&Xs[k][tm * 8];
            *(float4*)&a[4] = *(const float4*)&Xs[k][tm * 8 + 4];
            *(float4*)&b[0] = *(const float4*)&Ps[k][tn * 8];
            *(float4*)&b[4] = *(const float4*)&Ps[k][tn * 8 + 4];
            #pragma unroll
            for (int i = 0; i < 8; i++)
                #pragma unroll
                for (int j = 0; j < 8; j++)
                    acc[i][j] = fmaf(a[i], b[j], acc[i][j]);
        }
        __syncthreads();
    }

    // softmax per row (row's 256 slots live across the 32 lanes of this warp)
    float s0v[8];
    #pragma unroll
    for (int j = 0; j < 8; j++) s0v[j] = g_s0[tn * 8 + j];

    #pragma unroll
    for (int i = 0; i < 8; i++) {
        float mx = -1e30f;
        #pragma unroll
        for (int j = 0; j < 8; j++) { acc[i][j] += s0v[j]; mx = fmaxf(mx, acc[i][j]); }
        #pragma unroll
        for (int o = 16; o; o >>= 1) mx = fmaxf(mx, __shfl_xor_sync(0xffffffffu, mx, o));
        float sum = 0.f;
        #pragma unroll
        for (int j = 0; j < 8; j++) { acc[i][j] = __expf(acc[i][j] - mx); sum += acc[i][j]; }
        #pragma unroll
        for (int o = 16; o; o >>= 1) sum += __shfl_xor_sync(0xffffffffu, sum, o);
        float inv = 1.0f / sum;
        size_t row = (size_t)(row0 + tm * 8 + i);
        *(float4*)(g_w + row * MSLOTS + tn * 8) =
            make_float4(acc[i][0] * inv, acc[i][1] * inv, acc[i][2] * inv, acc[i][3] * inv);
        *(float4*)(g_w + row * MSLOTS + tn * 8 + 4) =
            make_float4(acc[i][4] * inv, acc[i][5] * inv, acc[i][6] * inv, acc[i][7] * inv);
    }
}

// ---------------------------------------------------------------------------
// out = w @ R + bo + x.  CTA: 64 rows x 256 cols, K = 256. 8x8 micro-tile.
// ---------------------------------------------------------------------------
__global__ __launch_bounds__(256) void out_kernel(
    const float* __restrict__ x, const float* __restrict__ bo,
    float* __restrict__ out)
{
    constexpr int BM = 64, BN = 256, BK = 16;
    __shared__ float Ws[BK][BM];     // 4 KB
    __shared__ float Rs[BK][BN];     // 16 KB
    const int row0 = blockIdx.y * BM;
    const int col0 = blockIdx.x * BN;
    const int tid = threadIdx.x;
    const int tm = tid >> 5, tn = tid & 31;
    float acc[8][8] = {};

    for (int kb = 0; kb < MSLOTS; kb += BK) {
        {   // w tile: 64 rows x 16 k, transpose into Ws[k][row]
            int r = tid >> 2, k0 = (tid & 3) * 4;
            float4 v = *(const float4*)(g_w + (size_t)(row0 + r) * MSLOTS + kb + k0);
            Ws[k0+0][r] = v.x; Ws[k0+1][r] = v.y; Ws[k0+2][r] = v.z; Ws[k0+3][r] = v.w;
        }
        {   // R tile: 16 k x 256 cols, direct copy (already [k][n] layout)
            int k = tid >> 4, n0 = (tid & 15) * 16;
            const float* rp = g_R + (size_t)(kb + k) * EDIM + col0 + n0;
            #pragma unroll
            for (int q = 0; q < 4; q++)
                *(float4*)&Rs[k][n0 + q * 4] = *(const float4*)(rp + q * 4);
        }
        __syncthreads();
        #pragma unroll
        for (int k = 0; k < BK; k++) {
            float a[8], b[8];
            *(float4*)&a[0] = *(const float4*)&Ws[k][tm * 8];
            *(float4*)&a[4] = *(const float4*)&Ws[k][tm * 8 + 4];
            *(float4*)&b[0] = *(const float4*)&Rs[k][tn * 8];
            *(float4*)&b[4] = *(const float4*)&Rs[k][tn * 8 + 4];
            #pragma unroll
            for (int i = 0; i < 8; i++)
                #pragma unroll
                for (int j = 0; j < 8; j++)
                    acc[i][j] = fmaf(a[i], b[j], acc[i][j]);
        }
        __syncthreads();
    }

    #pragma unroll
    for (int i = 0; i < 8; i++) {
        size_t row = (size_t)(row0 + tm * 8 + i);
        int col = col0 + tn * 8;
        float4 xv0 = *(const float4*)(x + row * EDIM + col);
        float4 xv1 = *(const float4*)(x + row * EDIM + col + 4);
        float4 bv0 = *(const float4*)(bo + col);
        float4 bv1 = *(const float4*)(bo + col + 4);
        float4 o0 = make_float4((acc[i][0] + bv0.x) + xv0.x, (acc[i][1] + bv0.y) + xv0.y,
                                (acc[i][2] + bv0.z) + xv0.z, (acc[i][3] + bv0.w) + xv0.w);
        float4 o1 = make_float4((acc[i][4] + bv1.x) + xv1.x, (acc[i][5] + bv1.y) + xv1.y,
                                (acc[i][6] + bv1.z) + xv1.z, (acc[i][7] + bv1.w) + xv1.w);
        *(float4*)(out + row * EDIM + col)     = o0;
        *(float4*)(out + row * EDIM + col + 4) = o1;
    }
}

// ---------------------------------------------------------------------------
// Launch
// ---------------------------------------------------------------------------
extern "C" void kernel_launch(void* const* d_in, const int* in_sizes, int n_in,
                              void* d_out, int out_size)
{
    (void)in_sizes; (void)n_in; (void)out_size;
    const float* x  = (const float*)d_in[0];   // [8,4096,1024]
    const float* Mb = (const float*)d_in[1];   // [256,1024]
    const float* Wq = (const float*)d_in[2];   // [1024,1024]
    const float* bq = (const float*)d_in[3];   // [1024]
    const float* Wo = (const float*)d_in[4];   // [1024,1024]
    const float* bo = (const float*)d_in[5];   // [1024]
    float* out = (float*)d_out;                // [8,4096,1024]

    precompute_kernel<<<dim3(EDIM / 64, MSLOTS / 64, 2), 256>>>(Mb, Wq, Wo);
    s0_kernel<<<MSLOTS, 32>>>(Mb, bq);
    scores_kernel<<<NROWS / 64, 256>>>(x);
    out_kernel<<<dim3(EDIM / 256, NROWS / 64), 256>>>(x, bo, out);
}

// round 2
// speedup vs baseline: 1.0040x; 1.0040x over previous
#include <cuda_runtime.h>

// Problem constants
#define EDIM   1024
#define MSLOTS 256
#define NROWS  32768   // 8 * 4096

// Scratch (no allocations allowed -> __device__ globals)
__device__ float g_P[MSLOTS * EDIM];                 // P = M @ Wq         [256,1024]
__device__ float g_R[MSLOTS * EDIM];                 // R = M @ Wo^T       [256,1024]
__device__ float g_s0[MSLOTS];                       // s0 = M @ bq        [256]
__device__ float g_w[(size_t)NROWS * MSLOTS];        // softmax weights    [32768,256]

// ---------------------------------------------------------------------------
// Precompute P (mode 0) and R (mode 1): C[m,n] = sum_k M[m,k] * B[k,n]
//   mode 0: B[k,n] = Wq[k*E + n]        (P = M @ Wq)
//   mode 1: B[k,n] = Wo[n*E + k]        (R = M @ Wo^T)
// Tile 64x64x32, 256 threads, 4x4 micro-tile.
// ---------------------------------------------------------------------------
__global__ __launch_bounds__(256) void precompute_kernel(
    const float* __restrict__ Mb, const float* __restrict__ Wq,
    const float* __restrict__ Wo)
{
    constexpr int BM = 64, BN = 64, BK = 32;
    __shared__ float As[BK][BM];
    __shared__ float Bs[BK][BN];
    const int mode = blockIdx.z;
    const int m0 = blockIdx.y * BM;
    const int n0 = blockIdx.x * BN;
    const int tid = threadIdx.x;
    const int tm = tid >> 4, tn = tid & 15;
    float acc[4][4] = {};

    for (int kb = 0; kb < EDIM; kb += BK) {
        // A tile: M rows m0..m0+63, k = kb..kb+31 (transpose into As[k][row])
        {
            int r = tid >> 2, k0 = (tid & 3) * 8;
            float4 v0 = *(const float4*)(Mb + (m0 + r) * EDIM + kb + k0);
            float4 v1 = *(const float4*)(Mb + (m0 + r) * EDIM + kb + k0 + 4);
            As[k0+0][r] = v0.x; As[k0+1][r] = v0.y; As[k0+2][r] = v0.z; As[k0+3][r] = v0.w;
            As[k0+4][r] = v1.x; As[k0+5][r] = v1.y; As[k0+6][r] = v1.z; As[k0+7][r] = v1.w;
        }
        if (mode == 0) {
            // Wq: rows = k (contiguous n) -> direct copy
            int k = tid >> 3, nq = (tid & 7) * 8;
            float4 v0 = *(const float4*)(Wq + (size_t)(kb + k) * EDIM + n0 + nq);
            float4 v1 = *(const float4*)(Wq + (size_t)(kb + k) * EDIM + n0 + nq + 4);
            *(float4*)&Bs[k][nq]     = v0;
            *(float4*)&Bs[k][nq + 4] = v1;
        } else {
            // Wo: B[k,n] = Wo[n*E + k] -> load along k, transpose into Bs[k][n]
            int n = tid >> 2, k0 = (tid & 3) * 8;
            float4 v0 = *(const float4*)(Wo + (size_t)(n0 + n) * EDIM + kb + k0);
            float4 v1 = *(const float4*)(Wo + (size_t)(n0 + n) * EDIM + kb + k0 + 4);
            Bs[k0+0][n] = v0.x; Bs[k0+1][n] = v0.y; Bs[k0+2][n] = v0.z; Bs[k0+3][n] = v0.w;
            Bs[k0+4][n] = v1.x; Bs[k0+5][n] = v1.y; Bs[k0+6][n] = v1.z; Bs[k0+7][n] = v1.w;
        }
        __syncthreads();
        #pragma unroll
        for (int k = 0; k < BK; k++) {
            float a[4], b[4];
            *(float4*)a = *(const float4*)&As[k][tm * 4];
            *(float4*)b = *(const float4*)&Bs[k][tn * 4];
            #pragma unroll
            for (int i = 0; i < 4; i++)
                #pragma unroll
                for (int j = 0; j < 4; j++)
                    acc[i][j] = fmaf(a[i], b[j], acc[i][j]);
        }
        __syncthreads();
    }
    float* C = mode ? g_R : g_P;
    #pragma unroll
    for (int i = 0; i < 4; i++) {
        int m = m0 + tm * 4 + i;
        *(float4*)(C + (size_t)m * EDIM + n0 + tn * 4) =
            make_float4(acc[i][0], acc[i][1], acc[i][2], acc[i][3]);
    }
}

// ---------------------------------------------------------------------------
// s0[m] = sum_e bq[e] * M[m,e].  One warp per slot.
// ---------------------------------------------------------------------------
__global__ void s0_kernel(const float* __restrict__ Mb, const float* __restrict__ bq)
{
    int m = blockIdx.x;
    int lane = threadIdx.x;
    float s = 0.f;
    #pragma unroll
    for (int c = 0; c < 8; c++) {
        int e = lane * 4 + c * 128;
        float4 mv = *(const float4*)(Mb + (size_t)m * EDIM + e);
        float4 bv = *(const float4*)(bq + e);
        s += mv.x * bv.x + mv.y * bv.y + mv.z * bv.z + mv.w * bv.w;
    }
    #pragma unroll
    for (int o = 16; o; o >>= 1) s += __shfl_xor_sync(0xffffffffu, s, o);
    if (lane == 0) g_s0[m] = s;
}

// ---------------------------------------------------------------------------
// scores + softmax fused: per CTA, 64 rows x all 256 slots, K=1024.
// scores[r,m] = sum_e x[r,e]*P[m,e] + s0[m]; w = softmax over m.
// 256 threads, 8x8 micro-tile; warp tm owns rows tm*8..tm*8+7 and the full
// 256-slot extent across its 32 lanes -> softmax via warp shuffles.
// ---------------------------------------------------------------------------
__global__ __launch_bounds__(256) void scores_kernel(const float* __restrict__ x)
{
    constexpr int BM = 64, BK = 32;
    __shared__ float Xs[BK][BM];       // 8 KB
    __shared__ float Ps[BK][MSLOTS];   // 32 KB
    const int row0 = blockIdx.x * BM;
    const int tid = threadIdx.x;
    const int tm = tid >> 5, tn = tid & 31;
    float acc[8][8] = {};

    for (int kb = 0; kb < EDIM; kb += BK) {
        {   // x tile: 64 rows x 32 k, transpose into Xs[k][row]
            int r = tid >> 2, k0 = (tid & 3) * 8;
            const float* xp = x + (size_t)(row0 + r) * EDIM + kb + k0;
            float4 v0 = *(const float4*)xp;
            float4 v1 = *(const float4*)(xp + 4);
            Xs[k0+0][r] = v0.x; Xs[k0+1][r] = v0.y; Xs[k0+2][r] = v0.z; Xs[k0+3][r] = v0.w;
            Xs[k0+4][r] = v1.x; Xs[k0+5][r] = v1.y; Xs[k0+6][r] = v1.z; Xs[k0+7][r] = v1.w;
        }
        {   // P tile: 256 m x 32 k, coalesced (8 threads per row), transpose
            int kq = (tid & 7) * 4;
            int mbase = tid >> 3;   // 0..31
            #pragma unroll
            for (int mm = 0; mm < MSLOTS; mm += 32) {
                int m = mbase + mm;
                float4 v = *(const float4*)(g_P + (size_t)m * EDIM + kb + kq);
                Ps[kq+0][m] = v.x; Ps[kq+1][m] = v.y; Ps[kq+2][m] = v.z; Ps[kq+3][m] = v.w;
            }
        }
        __syncthreads();
        #pragma unroll
        for (int k = 0; k < BK; k++) {
            float a[8], b[8];
            *(float4*)&a[0] = *(const float4*)&Xs[k][tm * 8];
            *(float4*)&a[4] = *(const float4*)&Xs[k][tm * 8 + 4];
            *(float4*)&b[0] = *(const float4*)&Ps[k][tn * 8];
            *(float4*)&b[4] = *(const float4*)&Ps[k][tn * 8 + 4];
            #pragma unroll
            for (int i = 0; i < 8; i++)
                #pragma unroll
                for (int j = 0; j < 8; j++)
                    acc[i][j] = fmaf(a[i], b[j], acc[i][j]);
        }
        __syncthreads();
    }

    // softmax per row (row's 256 slots live across the 32 lanes of this warp)
    float s0v[8];
    #pragma unroll
    for (int j = 0; j < 8; j++) s0v[j] = g_s0[tn * 8 + j];

    #pragma unroll
    for (int i = 0; i < 8; i++) {
        float mx = -1e30f;
        #pragma unroll
        for (int j = 0; j < 8; j++) { acc[i][j] += s0v[j]; mx = fmaxf(mx, acc[i][j]); }
        #pragma unroll
        for (int o = 16; o; o >>= 1) mx = fmaxf(mx, __shfl_xor_sync(0xffffffffu, mx, o));
        float sum = 0.f;
        #pragma unroll
        for (int j = 0; j < 8; j++) { acc[i][j] = __expf(acc[i][j] - mx); sum += acc[i][j]; }
        #pragma unroll
        for (int o = 16; o; o >>= 1) sum += __shfl_xor_sync(0xffffffffu, sum, o);
        float inv = 1.0f / sum;
        size_t row = (size_t)(row0 + tm * 8 + i);
        *(float4*)(g_w + row * MSLOTS + tn * 8) =
            make_float4(acc[i][0] * inv, acc[i][1] * inv, acc[i][2] * inv, acc[i][3] * inv);
        *(float4*)(g_w + row * MSLOTS + tn * 8 + 4) =
            make_float4(acc[i][4] * inv, acc[i][5] * inv, acc[i][6] * inv, acc[i][7] * inv);
    }
}

// ---------------------------------------------------------------------------
// out = w @ R + bo + x.  CTA: 64 rows x 256 cols, K = 256. 8x8 micro-tile.
// ---------------------------------------------------------------------------
__global__ __launch_bounds__(256) void out_kernel(
    const float* __restrict__ x, const float* __restrict__ bo,
    float* __restrict__ out)
{
    constexpr int BM = 64, BN = 256, BK = 16;
    __shared__ float Ws[BK][BM];     // 4 KB
    __shared__ float Rs[BK][BN];     // 16 KB
    const int row0 = blockIdx.y * BM;
    const int col0 = blockIdx.x * BN;
    const int tid = threadIdx.x;
    const int tm = tid >> 5, tn = tid & 31;
    float acc[8][8] = {};

    for (int kb = 0; kb < MSLOTS; kb += BK) {
        {   // w tile: 64 rows x 16 k, transpose into Ws[k][row]
            int r = tid >> 2, k0 = (tid & 3) * 4;
            float4 v = *(const float4*)(g_w + (size_t)(row0 + r) * MSLOTS + kb + k0);
            Ws[k0+0][r] = v.x; Ws[k0+1][r] = v.y; Ws[k0+2][r] = v.z; Ws[k0+3][r] = v.w;
        }
        {   // R tile: 16 k x 256 cols, direct copy (already [k][n] layout)
            int k = tid >> 4, n0 = (tid & 15) * 16;
            const float* rp = g_R + (size_t)(kb + k) * EDIM + col0 + n0;
            #pragma unroll
            for (int q = 0; q < 4; q++)
                *(float4*)&Rs[k][n0 + q * 4] = *(const float4*)(rp + q * 4);
        }
        __syncthreads();
        #pragma unroll
        for (int k = 0; k < BK; k++) {
            float a[8], b[8];
            *(float4*)&a[0] = *(const float4*)&Ws[k][tm * 8];
            *(float4*)&a[4] = *(const float4*)&Ws[k][tm * 8 + 4];
            *(float4*)&b[0] = *(const float4*)&Rs[k][tn * 8];
            *(float4*)&b[4] = *(const float4*)&Rs[k][tn * 8 + 4];
            #pragma unroll
            for (int i = 0; i < 8; i++)
                #pragma unroll
                for (int j = 0; j < 8; j++)
                    acc[i][j] = fmaf(a[i], b[j], acc[i][j]);
        }
        __syncthreads();
    }

    #pragma unroll
    for (int i = 0; i < 8; i++) {
        size_t row = (size_t)(row0 + tm * 8 + i);
        int col = col0 + tn * 8;
        float4 xv0 = *(const float4*)(x + row * EDIM + col);
        float4 xv1 = *(const float4*)(x + row * EDIM + col + 4);
        float4 bv0 = *(const float4*)(bo + col);
        float4 bv1 = *(const float4*)(bo + col + 4);
        float4 o0 = make_float4((acc[i][0] + bv0.x) + xv0.x, (acc[i][1] + bv0.y) + xv0.y,
                                (acc[i][2] + bv0.z) + xv0.z, (acc[i][3] + bv0.w) + xv0.w);
        float4 o1 = make_float4((acc[i][4] + bv1.x) + xv1.x, (acc[i][5] + bv1.y) + xv1.y,
                                (acc[i][6] + bv1.z) + xv1.z, (acc[i][7] + bv1.w) + xv1.w);
        *(float4*)(out + row * EDIM + col)     = o0;
        *(float4*)(out + row * EDIM + col + 4) = o1;
    }
}

// ---------------------------------------------------------------------------
// Launch
// ---------------------------------------------------------------------------
extern "C" void kernel_launch(void* const* d_in, const int* in_sizes, int n_in,
                              void* d_out, int out_size)
{
    (void)in_sizes; (void)n_in; (void)out_size;
    const float* x  = (const float*)d_in[0];   // [8,4096,1024]
    const float* Mb = (const float*)d_in[1];   // [256,1024]
    const float* Wq = (const float*)d_in[2];   // [1024,1024]
    const float* bq = (const float*)d_in[3];   // [1024]
    const float* Wo = (const float*)d_in[4];   // [1024,1024]
    const float* bo = (const float*)d_in[5];   // [1024]
    float* out = (float*)d_out;                // [8,4096,1024]

    precompute_kernel<<<dim3(EDIM / 64, MSLOTS / 64, 2), 256>>>(Mb, Wq, Wo);
    s0_kernel<<<MSLOTS, 32>>>(Mb, bq);
    scores_kernel<<<NROWS / 64, 256>>>(x);
    out_kernel<<<dim3(EDIM / 256, NROWS / 64), 256>>>(x, bo, out);
}

// round 4
// speedup vs baseline: 2.6297x; 2.6193x over previous
#include <cuda_runtime.h>
#include <cstdint>

#define EDIM   1024
#define MSLOTS 256
#define NROWS  32768

// Scratch (no allocations -> __device__ globals). Values pre-rounded to tf32.
__device__ float g_P [MSLOTS * EDIM];              // P  = M @ Wq       [slot, e]
__device__ float g_Rt[EDIM * MSLOTS];              // Rt = (M @ Wo^T)^T [e, slot]
__device__ float g_s0[MSLOTS];                     // s0 = M @ bq  (full fp32)
__device__ float g_w [(size_t)NROWS * MSLOTS];     // softmax weights   [row, slot]

// ---------------------------------------------------------------------------
// Helpers
// ---------------------------------------------------------------------------
__device__ __forceinline__ uint32_t smem_u32(const void* p) {
    uint32_t a;
    asm("{ .reg .u64 t; cvta.to.shared.u64 t, %1; cvt.u32.u64 %0, t; }" : "=r"(a) : "l"(p));
    return a;
}
__device__ __forceinline__ void cp16(uint32_t dst, const void* src) {
    asm volatile("cp.async.cg.shared.global [%0], [%1], 16;" :: "r"(dst), "l"(src));
}
#define CP_COMMIT() asm volatile("cp.async.commit_group;" ::: "memory")
#define CP_WAIT(n)  asm volatile("cp.async.wait_group %0;" :: "n"(n) : "memory")

#define LDSM4(r0, r1, r2, r3, addr) \
    asm volatile("ldmatrix.sync.aligned.m8n8.x4.shared.b16 {%0,%1,%2,%3}, [%4];" \
        : "=r"(r0), "=r"(r1), "=r"(r2), "=r"(r3) : "r"(addr))

#define MMA_TF32(c, a, b) \
    asm volatile("mma.sync.aligned.m16n8k8.row.col.f32.tf32.tf32.f32 " \
        "{%0,%1,%2,%3}, {%4,%5,%6,%7}, {%8,%9}, {%0,%1,%2,%3};" \
        : "+f"((c)[0]), "+f"((c)[1]), "+f"((c)[2]), "+f"((c)[3]) \
        : "r"((a)[0]), "r"((a)[1]), "r"((a)[2]), "r"((a)[3]), "r"((b)[0]), "r"((b)[1]))

__device__ __forceinline__ float to_tf32(float v) {
    uint32_t u;
    asm("cvt.rna.tf32.f32 %0, %1;" : "=r"(u) : "f"(v));
    return __uint_as_float(u);
}
__device__ __forceinline__ void cvt_tf32_r(uint32_t& u) {
    asm("cvt.rna.tf32.f32 %0, %0;" : "+r"(u));
}

// Padded K stride (floats): 16 + 4 -> 80B rows, conflict-free ldmatrix
#define LDK 20

// ---------------------------------------------------------------------------
// Precompute P (mode 0) and Rt (mode 1), tf32-rounded outputs
// ---------------------------------------------------------------------------
__global__ __launch_bounds__(256) void precompute_kernel(
    const float* __restrict__ Mb, const float* __restrict__ Wq,
    const float* __restrict__ Wo)
{
    constexpr int BM = 64, BN = 64, BK = 32;
    __shared__ float As[BK][BM];
    __shared__ float Bs[BK][BN];
    const int mode = blockIdx.z;
    const int m0 = blockIdx.y * BM;
    const int n0 = blockIdx.x * BN;
    const int tid = threadIdx.x;
    const int tm = tid >> 4, tn = tid & 15;
    float acc[4][4] = {};

    for (int kb = 0; kb < EDIM; kb += BK) {
        {
            int r = tid >> 2, k0 = (tid & 3) * 8;
            float4 v0 = *(const float4*)(Mb + (m0 + r) * EDIM + kb + k0);
            float4 v1 = *(const float4*)(Mb + (m0 + r) * EDIM + kb + k0 + 4);
            As[k0+0][r] = v0.x; As[k0+1][r] = v0.y; As[k0+2][r] = v0.z; As[k0+3][r] = v0.w;
            As[k0+4][r] = v1.x; As[k0+5][r] = v1.y; As[k0+6][r] = v1.z; As[k0+7][r] = v1.w;
        }
        if (mode == 0) {
            int k = tid >> 3, nq = (tid & 7) * 8;
            float4 v0 = *(const float4*)(Wq + (size_t)(kb + k) * EDIM + n0 + nq);
            float4 v1 = *(const float4*)(Wq + (size_t)(kb + k) * EDIM + n0 + nq + 4);
            *(float4*)&Bs[k][nq]     = v0;
            *(float4*)&Bs[k][nq + 4] = v1;
        } else {
            int n = tid >> 2, k0 = (tid & 3) * 8;
            float4 v0 = *(const float4*)(Wo + (size_t)(n0 + n) * EDIM + kb + k0);
            float4 v1 = *(const float4*)(Wo + (size_t)(n0 + n) * EDIM + kb + k0 + 4);
            Bs[k0+0][n] = v0.x; Bs[k0+1][n] = v0.y; Bs[k0+2][n] = v0.z; Bs[k0+3][n] = v0.w;
            Bs[k0+4][n] = v1.x; Bs[k0+5][n] = v1.y; Bs[k0+6][n] = v1.z; Bs[k0+7][n] = v1.w;
        }
        __syncthreads();
        #pragma unroll
        for (int k = 0; k < BK; k++) {
            float a[4], b[4];
            *(float4*)a = *(const float4*)&As[k][tm * 4];
            *(float4*)b = *(const float4*)&Bs[k][tn * 4];
            #pragma unroll
            for (int i = 0; i < 4; i++)
                #pragma unroll
                for (int j = 0; j < 4; j++)
                    acc[i][j] = fmaf(a[i], b[j], acc[i][j]);
        }
        __syncthreads();
    }
    if (mode == 0) {
        #pragma unroll
        for (int i = 0; i < 4; i++) {
            int m = m0 + tm * 4 + i;
            *(float4*)(g_P + (size_t)m * EDIM + n0 + tn * 4) =
                make_float4(to_tf32(acc[i][0]), to_tf32(acc[i][1]),
                            to_tf32(acc[i][2]), to_tf32(acc[i][3]));
        }
    } else {
        #pragma unroll
        for (int i = 0; i < 4; i++)
            #pragma unroll
            for (int j = 0; j < 4; j++)
                g_Rt[(size_t)(n0 + tn * 4 + j) * MSLOTS + (m0 + tm * 4 + i)] = to_tf32(acc[i][j]);
    }
}

__global__ void s0_kernel(const float* __restrict__ Mb, const float* __restrict__ bq)
{
    int m = blockIdx.x;
    int lane = threadIdx.x;
    float s = 0.f;
    #pragma unroll
    for (int c = 0; c < 8; c++) {
        int e = lane * 4 + c * 128;
        float4 mv = *(const float4*)(Mb + (size_t)m * EDIM + e);
        float4 bv = *(const float4*)(bq + e);
        s += mv.x * bv.x + mv.y * bv.y + mv.z * bv.z + mv.w * bv.w;
    }
    #pragma unroll
    for (int o = 16; o; o >>= 1) s += __shfl_xor_sync(0xffffffffu, s, o);
    if (lane == 0) g_s0[m] = s;
}

// ---------------------------------------------------------------------------
// scores + softmax: CTA = 64 rows x 256 slots, K=1024, mma.sync tf32.
// 8 warps in 2x4 grid, warp tile 32x64.
// ---------------------------------------------------------------------------
#define S_AST (64 * LDK * 4)          // 5120
#define S_BST (256 * LDK * 4)         // 20480
#define S_ST  (S_AST + S_BST)         // 25600
#define S_OFF_S0  0
#define S_OFF_RED 1024
#define S_OFF_STG 2048
#define S_SMEM (S_OFF_STG + 4 * S_ST) // 104448

__global__ __launch_bounds__(256, 1) void scores_tc(const float* __restrict__ x)
{
    extern __shared__ char smem[];
    const uint32_t sb = smem_u32(smem);
    const int tid = threadIdx.x;
    const int lane = tid & 31, wid = tid >> 5;
    const int wm = wid >> 2, wn = wid & 3;       // warp grid 2x4
    const int g = lane >> 2, q = lane & 3;
    const int row0 = blockIdx.x * 64;

    if (tid < 64) ((float4*)(smem + S_OFF_S0))[tid] = ((const float4*)g_s0)[tid];

    auto load_stage = [&](int buf, int kb) {
        uint32_t ab = sb + S_OFF_STG + buf * S_ST;
        uint32_t bb = ab + S_AST;
        {   // A: x[row0..row0+63, kb..kb+15]
            int r = tid >> 2, t = tid & 3;
            cp16(ab + (r * LDK + t * 4) * 4, x + (size_t)(row0 + r) * EDIM + kb + t * 4);
        }
        #pragma unroll
        for (int i = 0; i < 4; i++) {   // B: g_P[0..255, kb..kb+15]
            int idx = tid + i * 256;
            int r = idx >> 2, t = idx & 3;
            cp16(bb + (r * LDK + t * 4) * 4, g_P + (size_t)r * EDIM + kb + t * 4);
        }
    };

    float acc[2][8][4] = {};
    #pragma unroll
    for (int p = 0; p < 3; p++) { load_stage(p, p * 16); CP_COMMIT(); }

    for (int s = 0; s < 64; s++) {
        CP_WAIT(2);
        __syncthreads();
        if (s + 3 < 64) load_stage((s + 3) & 3, (s + 3) * 16);
        CP_COMMIT();

        uint32_t aB = sb + S_OFF_STG + (s & 3) * S_ST;
        uint32_t bB = aB + S_AST;
        #pragma unroll
        for (int k8 = 0; k8 < 16; k8 += 8) {
            uint32_t af[2][4], bf[8][2];
            #pragma unroll
            for (int mb = 0; mb < 2; mb++) {
                int row = wm * 32 + mb * 16 + ((lane >> 3) & 1) * 8 + (lane & 7);
                int kof = k8 + ((lane >> 4) << 2);
                LDSM4(af[mb][0], af[mb][1], af[mb][2], af[mb][3],
                      aB + (row * LDK + kof) * 4);
            }
            #pragma unroll
            for (int nb2 = 0; nb2 < 4; nb2++) {
                int n = wn * 64 + nb2 * 16 + ((lane >> 4) & 1) * 8 + (lane & 7);
                int kof = k8 + ((lane >> 3) & 1) * 4;
                LDSM4(bf[nb2*2][0], bf[nb2*2][1], bf[nb2*2+1][0], bf[nb2*2+1][1],
                      bB + (n * LDK + kof) * 4);
            }
            // x is raw fp32 -> round A frags to tf32 (B already rounded)
            #pragma unroll
            for (int mb = 0; mb < 2; mb++)
                #pragma unroll
                for (int i = 0; i < 4; i++) cvt_tf32_r(af[mb][i]);
            #pragma unroll
            for (int mb = 0; mb < 2; mb++)
                #pragma unroll
                for (int nb = 0; nb < 8; nb++)
                    MMA_TF32(acc[mb][nb], af[mb], bf[nb]);
        }
    }

    // ---- softmax epilogue ----
    const float* s0s = (const float*)(smem + S_OFF_S0);
    float* red = (float*)(smem + S_OFF_RED);   // [64 rows][4 col-warps]

    #pragma unroll
    for (int nb = 0; nb < 8; nb++) {
        float2 sp = *(const float2*)(s0s + wn * 64 + nb * 8 + q * 2);
        #pragma unroll
        for (int mb = 0; mb < 2; mb++) {
            acc[mb][nb][0] += sp.x; acc[mb][nb][1] += sp.y;
            acc[mb][nb][2] += sp.x; acc[mb][nb][3] += sp.y;
        }
    }
    float mx[2][2], sum[2][2];
    #pragma unroll
    for (int mb = 0; mb < 2; mb++)
        #pragma unroll
        for (int r = 0; r < 2; r++) {
            float m = -1e30f;
            #pragma unroll
            for (int nb = 0; nb < 8; nb++)
                m = fmaxf(m, fmaxf(acc[mb][nb][r*2], acc[mb][nb][r*2+1]));
            m = fmaxf(m, __shfl_xor_sync(0xffffffffu, m, 1));
            m = fmaxf(m, __shfl_xor_sync(0xffffffffu, m, 2));
            if (q == 0) red[(wm * 32 + mb * 16 + g + r * 8) * 4 + wn] = m;
            mx[mb][r] = m;
        }
    __syncthreads();
    #pragma unroll
    for (int mb = 0; mb < 2; mb++)
        #pragma unroll
        for (int r = 0; r < 2; r++) {
            int row = wm * 32 + mb * 16 + g + r * 8;
            float4 rv = *(const float4*)(red + row * 4);
            mx[mb][r] = fmaxf(fmaxf(rv.x, rv.y), fmaxf(rv.z, rv.w));
        }
    __syncthreads();
    #pragma unroll
    for (int mb = 0; mb < 2; mb++)
        #pragma unroll
        for (int r = 0; r < 2; r++) {
            float s = 0.f;
            #pragma unroll
            for (int nb = 0; nb < 8; nb++) {
                float e0 = __expf(acc[mb][nb][r*2]   - mx[mb][r]);
                float e1 = __expf(acc[mb][nb][r*2+1] - mx[mb][r]);
                acc[mb][nb][r*2] = e0; acc[mb][nb][r*2+1] = e1;
                s += e0 + e1;
            }
            s += __shfl_xor_sync(0xffffffffu, s, 1);
            s += __shfl_xor_sync(0xffffffffu, s, 2);
            if (q == 0) red[(wm * 32 + mb * 16 + g + r * 8) * 4 + wn] = s;
            sum[mb][r] = s;
        }
    __syncthreads();
    #pragma unroll
    for (int mb = 0; mb < 2; mb++)
        #pragma unroll
        for (int r = 0; r < 2; r++) {
            int row = wm * 32 + mb * 16 + g + r * 8;
            float4 rv = *(const float4*)(red + row * 4);
            float inv = 1.f / (rv.x + rv.y + rv.z + rv.w);
            size_t grow = (size_t)(row0 + row);
            #pragma unroll
            for (int nb = 0; nb < 8; nb++) {
                float2 o;
                o.x = to_tf32(acc[mb][nb][r*2]   * inv);
                o.y = to_tf32(acc[mb][nb][r*2+1] * inv);
                *(float2*)(g_w + grow * MSLOTS + wn * 64 + nb * 8 + q * 2) = o;
            }
        }
}

// ---------------------------------------------------------------------------
// out = w @ Rt^T + bo + x: CTA = 128 rows x 128 cols, K=256, mma.sync tf32.
// 8 warps in 2x4 grid, warp tile 64x32.
// ---------------------------------------------------------------------------
#define O_AST (128 * LDK * 4)         // 10240
#define O_BST (128 * LDK * 4)         // 10240
#define O_ST  (O_AST + O_BST)         // 20480
#define O_SMEM (4 * O_ST)             // 81920

__global__ __launch_bounds__(256, 1) void out_tc(
    const float* __restrict__ x, const float* __restrict__ bo,
    float* __restrict__ out)
{
    extern __shared__ char smem[];
    const uint32_t sb = smem_u32(smem);
    const int tid = threadIdx.x;
    const int lane = tid & 31, wid = tid >> 5;
    const int wm = wid >> 2, wn = wid & 3;
    const int g = lane >> 2, q = lane & 3;
    const int row0 = blockIdx.y * 128;
    const int col0 = blockIdx.x * 128;

    auto load_stage = [&](int buf, int kb) {
        uint32_t ab = sb + buf * O_ST;
        uint32_t bb = ab + O_AST;
        #pragma unroll
        for (int i = 0; i < 2; i++) {   // A: g_w[row0..+127, kb..kb+15]
            int idx = tid + i * 256;
            int r = idx >> 2, t = idx & 3;
            cp16(ab + (r * LDK + t * 4) * 4, g_w + (size_t)(row0 + r) * MSLOTS + kb + t * 4);
        }
        #pragma unroll
        for (int i = 0; i < 2; i++) {   // B: g_Rt[col0..+127, kb..kb+15]
            int idx = tid + i * 256;
            int r = idx >> 2, t = idx & 3;
            cp16(bb + (r * LDK + t * 4) * 4, g_Rt + (size_t)(col0 + r) * MSLOTS + kb + t * 4);
        }
    };

    float acc[4][4][4] = {};
    #pragma unroll
    for (int p = 0; p < 3; p++) { load_stage(p, p * 16); CP_COMMIT(); }

    for (int s = 0; s < 16; s++) {
        CP_WAIT(2);
        __syncthreads();
        if (s + 3 < 16) load_stage((s + 3) & 3, (s + 3) * 16);
        CP_COMMIT();

        uint32_t aB = sb + (s & 3) * O_ST;
        uint32_t bB = aB + O_AST;
        #pragma unroll
        for (int k8 = 0; k8 < 16; k8 += 8) {
            uint32_t af[4][4], bf[4][2];
            #pragma unroll
            for (int mb = 0; mb < 4; mb++) {
                int row = wm * 64 + mb * 16 + ((lane >> 3) & 1) * 8 + (lane & 7);
                int kof = k8 + ((lane >> 4) << 2);
                LDSM4(af[mb][0], af[mb][1], af[mb][2], af[mb][3],
                      aB + (row * LDK + kof) * 4);
            }
            #pragma unroll
            for (int nb2 = 0; nb2 < 2; nb2++) {
                int n = wn * 32 + nb2 * 16 + ((lane >> 4) & 1) * 8 + (lane & 7);
                int kof = k8 + ((lane >> 3) & 1) * 4;
                LDSM4(bf[nb2*2][0], bf[nb2*2][1], bf[nb2*2+1][0], bf[nb2*2+1][1],
                      bB + (n * LDK + kof) * 4);
            }
            // both operands pre-rounded to tf32 -> no cvt needed
            #pragma unroll
            for (int mb = 0; mb < 4; mb++)
                #pragma unroll
                for (int nb = 0; nb < 4; nb++)
                    MMA_TF32(acc[mb][nb], af[mb], bf[nb]);
        }
    }

    // ---- epilogue: + bo + x ----
    #pragma unroll
    for (int mb = 0; mb < 4; mb++)
        #pragma unroll
        for (int r = 0; r < 2; r++) {
            size_t row = (size_t)(row0 + wm * 64 + mb * 16 + g + r * 8);
            #pragma unroll
            for (int nb = 0; nb < 4; nb++) {
                int col = col0 + wn * 32 + nb * 8 + q * 2;
                float2 xv = *(const float2*)(x + row * EDIM + col);
                float2 bv = *(const float2*)(bo + col);
                float2 o;
                o.x = acc[mb][nb][r*2]   + bv.x + xv.x;
                o.y = acc[mb][nb][r*2+1] + bv.y + xv.y;
                *(float2*)(out + row * EDIM + col) = o;
            }
        }
}

// ---------------------------------------------------------------------------
// Launch
// ---------------------------------------------------------------------------
extern "C" void kernel_launch(void* const* d_in, const int* in_sizes, int n_in,
                              void* d_out, int out_size)
{
    (void)in_sizes; (void)n_in; (void)out_size;
    const float* x  = (const float*)d_in[0];
    const float* Mb = (const float*)d_in[1];
    const float* Wq = (const float*)d_in[2];
    const float* bq = (const float*)d_in[3];
    const float* Wo = (const float*)d_in[4];
    const float* bo = (const float*)d_in[5];
    float* out = (float*)d_out;

    cudaFuncSetAttribute(scores_tc, cudaFuncAttributeMaxDynamicSharedMemorySize, S_SMEM);
    cudaFuncSetAttribute(out_tc,    cudaFuncAttributeMaxDynamicSharedMemorySize, O_SMEM);

    precompute_kernel<<<dim3(EDIM / 64, MSLOTS / 64, 2), 256>>>(Mb, Wq, Wo);
    s0_kernel<<<MSLOTS, 32>>>(Mb, bq);
    scores_tc<<<NROWS / 64, 256, S_SMEM>>>(x);
    out_tc<<<dim3(EDIM / 128, NROWS / 128), 256, O_SMEM>>>(x, bo, out);
}

// round 5
// speedup vs baseline: 2.7505x; 1.0459x over previous
#include <cuda_runtime.h>
#include <cstdint>

#define EDIM   1024
#define MSLOTS 256
#define NROWS  32768

// Scratch (no allocations -> __device__ globals). Values pre-rounded to tf32.
__device__ float g_P [MSLOTS * EDIM];              // P  = M @ Wq       [slot, e]
__device__ float g_Rt[EDIM * MSLOTS];              // Rt = (M @ Wo^T)^T [e, slot]
__device__ float g_s0[MSLOTS];                     // s0 = M @ bq  (full fp32)
__device__ float g_w [(size_t)NROWS * MSLOTS];     // softmax weights   [row, slot]

// ---------------------------------------------------------------------------
// Helpers
// ---------------------------------------------------------------------------
__device__ __forceinline__ uint32_t smem_u32(const void* p) {
    uint32_t a;
    asm("{ .reg .u64 t; cvta.to.shared.u64 t, %1; cvt.u32.u64 %0, t; }" : "=r"(a) : "l"(p));
    return a;
}
__device__ __forceinline__ void cp16(uint32_t dst, const void* src) {
    asm volatile("cp.async.cg.shared.global [%0], [%1], 16;" :: "r"(dst), "l"(src));
}
#define CP_COMMIT() asm volatile("cp.async.commit_group;" ::: "memory")
#define CP_WAIT(n)  asm volatile("cp.async.wait_group %0;" :: "n"(n) : "memory")

#define LDSM4(r0, r1, r2, r3, addr) \
    asm volatile("ldmatrix.sync.aligned.m8n8.x4.shared.b16 {%0,%1,%2,%3}, [%4];" \
        : "=r"(r0), "=r"(r1), "=r"(r2), "=r"(r3) : "r"(addr))

#define MMA_TF32(c, a, b) \
    asm volatile("mma.sync.aligned.m16n8k8.row.col.f32.tf32.tf32.f32 " \
        "{%0,%1,%2,%3}, {%4,%5,%6,%7}, {%8,%9}, {%0,%1,%2,%3};" \
        : "+f"((c)[0]), "+f"((c)[1]), "+f"((c)[2]), "+f"((c)[3]) \
        : "r"((a)[0]), "r"((a)[1]), "r"((a)[2]), "r"((a)[3]), "r"((b)[0]), "r"((b)[1]))

__device__ __forceinline__ float to_tf32(float v) {
    uint32_t u;
    asm("cvt.rna.tf32.f32 %0, %1;" : "=r"(u) : "f"(v));
    return __uint_as_float(u);
}
__device__ __forceinline__ void cvt_tf32_r(uint32_t& u) {
    asm("cvt.rna.tf32.f32 %0, %0;" : "+r"(u));
}

// Padded K stride (floats): 16 + 4 -> 80B rows, conflict-free ldmatrix
#define LDK 20

// ---------------------------------------------------------------------------
// Precompute P (mode 0) and Rt (mode 1), tf32-rounded outputs
// ---------------------------------------------------------------------------
__global__ __launch_bounds__(256) void precompute_kernel(
    const float* __restrict__ Mb, const float* __restrict__ Wq,
    const float* __restrict__ Wo)
{
    constexpr int BM = 64, BN = 64, BK = 32;
    __shared__ float As[BK][BM];
    __shared__ float Bs[BK][BN];
    const int mode = blockIdx.z;
    const int m0 = blockIdx.y * BM;
    const int n0 = blockIdx.x * BN;
    const int tid = threadIdx.x;
    const int tm = tid >> 4, tn = tid & 15;
    float acc[4][4] = {};

    for (int kb = 0; kb < EDIM; kb += BK) {
        {
            int r = tid >> 2, k0 = (tid & 3) * 8;
            float4 v0 = *(const float4*)(Mb + (m0 + r) * EDIM + kb + k0);
            float4 v1 = *(const float4*)(Mb + (m0 + r) * EDIM + kb + k0 + 4);
            As[k0+0][r] = v0.x; As[k0+1][r] = v0.y; As[k0+2][r] = v0.z; As[k0+3][r] = v0.w;
            As[k0+4][r] = v1.x; As[k0+5][r] = v1.y; As[k0+6][r] = v1.z; As[k0+7][r] = v1.w;
        }
        if (mode == 0) {
            int k = tid >> 3, nq = (tid & 7) * 8;
            float4 v0 = *(const float4*)(Wq + (size_t)(kb + k) * EDIM + n0 + nq);
            float4 v1 = *(const float4*)(Wq + (size_t)(kb + k) * EDIM + n0 + nq + 4);
            *(float4*)&Bs[k][nq]     = v0;
            *(float4*)&Bs[k][nq + 4] = v1;
        } else {
            int n = tid >> 2, k0 = (tid & 3) * 8;
            float4 v0 = *(const float4*)(Wo + (size_t)(n0 + n) * EDIM + kb + k0);
            float4 v1 = *(const float4*)(Wo + (size_t)(n0 + n) * EDIM + kb + k0 + 4);
            Bs[k0+0][n] = v0.x; Bs[k0+1][n] = v0.y; Bs[k0+2][n] = v0.z; Bs[k0+3][n] = v0.w;
            Bs[k0+4][n] = v1.x; Bs[k0+5][n] = v1.y; Bs[k0+6][n] = v1.z; Bs[k0+7][n] = v1.w;
        }
        __syncthreads();
        #pragma unroll
        for (int k = 0; k < BK; k++) {
            float a[4], b[4];
            *(float4*)a = *(const float4*)&As[k][tm * 4];
            *(float4*)b = *(const float4*)&Bs[k][tn * 4];
            #pragma unroll
            for (int i = 0; i < 4; i++)
                #pragma unroll
                for (int j = 0; j < 4; j++)
                    acc[i][j] = fmaf(a[i], b[j], acc[i][j]);
        }
        __syncthreads();
    }
    if (mode == 0) {
        #pragma unroll
        for (int i = 0; i < 4; i++) {
            int m = m0 + tm * 4 + i;
            *(float4*)(g_P + (size_t)m * EDIM + n0 + tn * 4) =
                make_float4(to_tf32(acc[i][0]), to_tf32(acc[i][1]),
                            to_tf32(acc[i][2]), to_tf32(acc[i][3]));
        }
    } else {
        #pragma unroll
        for (int i = 0; i < 4; i++)
            #pragma unroll
            for (int j = 0; j < 4; j++)
                g_Rt[(size_t)(n0 + tn * 4 + j) * MSLOTS + (m0 + tm * 4 + i)] = to_tf32(acc[i][j]);
    }
}

__global__ void s0_kernel(const float* __restrict__ Mb, const float* __restrict__ bq)
{
    int m = blockIdx.x;
    int lane = threadIdx.x;
    float s = 0.f;
    #pragma unroll
    for (int c = 0; c < 8; c++) {
        int e = lane * 4 + c * 128;
        float4 mv = *(const float4*)(Mb + (size_t)m * EDIM + e);
        float4 bv = *(const float4*)(bq + e);
        s += mv.x * bv.x + mv.y * bv.y + mv.z * bv.z + mv.w * bv.w;
    }
    #pragma unroll
    for (int o = 16; o; o >>= 1) s += __shfl_xor_sync(0xffffffffu, s, o);
    if (lane == 0) g_s0[m] = s;
}

// ---------------------------------------------------------------------------
// scores + softmax: CTA = 64 rows x 256 slots, K=1024, mma.sync tf32.
// 512 threads = 16 warps in 2x8 grid, warp tile 32x32.
// ---------------------------------------------------------------------------
#define S_AST (64 * LDK * 4)          // 5120
#define S_BST (256 * LDK * 4)         // 20480
#define S_ST  (S_AST + S_BST)         // 25600
#define S_OFF_S0  0
#define S_OFF_RED 1024                // 64 rows x 8 col-warps x 4B = 2KB
#define S_OFF_STG 4096
#define S_SMEM (S_OFF_STG + 4 * S_ST) // 106496

__global__ __launch_bounds__(512, 1) void scores_tc(const float* __restrict__ x)
{
    extern __shared__ char smem[];
    const uint32_t sb = smem_u32(smem);
    const int tid = threadIdx.x;
    const int lane = tid & 31, wid = tid >> 5;
    const int wm = wid >> 3, wn = wid & 7;       // warp grid 2x8
    const int g = lane >> 2, q = lane & 3;
    const int row0 = blockIdx.x * 64;

    if (tid < 64) ((float4*)(smem + S_OFF_S0))[tid] = ((const float4*)g_s0)[tid];

    auto load_stage = [&](int buf, int kb) {
        uint32_t ab = sb + S_OFF_STG + buf * S_ST;
        uint32_t bb = ab + S_AST;
        if (tid < 256) {   // A: x[row0..row0+63, kb..kb+15]
            int r = tid >> 2, t = tid & 3;
            cp16(ab + (r * LDK + t * 4) * 4, x + (size_t)(row0 + r) * EDIM + kb + t * 4);
        }
        #pragma unroll
        for (int i = 0; i < 2; i++) {   // B: g_P[0..255, kb..kb+15]
            int idx = tid + i * 512;
            int r = idx >> 2, t = idx & 3;
            cp16(bb + (r * LDK + t * 4) * 4, g_P + (size_t)r * EDIM + kb + t * 4);
        }
    };

    float acc[2][4][4] = {};
    #pragma unroll
    for (int p = 0; p < 3; p++) { load_stage(p, p * 16); CP_COMMIT(); }

    for (int s = 0; s < 64; s++) {
        CP_WAIT(2);
        __syncthreads();
        if (s + 3 < 64) load_stage((s + 3) & 3, (s + 3) * 16);
        CP_COMMIT();

        uint32_t aB = sb + S_OFF_STG + (s & 3) * S_ST;
        uint32_t bB = aB + S_AST;
        #pragma unroll
        for (int k8 = 0; k8 < 16; k8 += 8) {
            uint32_t af[2][4], bf[4][2];
            #pragma unroll
            for (int mb = 0; mb < 2; mb++) {
                int row = wm * 32 + mb * 16 + ((lane >> 3) & 1) * 8 + (lane & 7);
                int kof = k8 + ((lane >> 4) << 2);
                LDSM4(af[mb][0], af[mb][1], af[mb][2], af[mb][3],
                      aB + (row * LDK + kof) * 4);
            }
            #pragma unroll
            for (int nb2 = 0; nb2 < 2; nb2++) {
                int n = wn * 32 + nb2 * 16 + ((lane >> 4) & 1) * 8 + (lane & 7);
                int kof = k8 + ((lane >> 3) & 1) * 4;
                LDSM4(bf[nb2*2][0], bf[nb2*2][1], bf[nb2*2+1][0], bf[nb2*2+1][1],
                      bB + (n * LDK + kof) * 4);
            }
            // x is raw fp32 -> round A frags to tf32 (B already rounded)
            #pragma unroll
            for (int mb = 0; mb < 2; mb++)
                #pragma unroll
                for (int i = 0; i < 4; i++) cvt_tf32_r(af[mb][i]);
            #pragma unroll
            for (int mb = 0; mb < 2; mb++)
                #pragma unroll
                for (int nb = 0; nb < 4; nb++)
                    MMA_TF32(acc[mb][nb], af[mb], bf[nb]);
        }
    }

    // ---- softmax epilogue ----
    const float* s0s = (const float*)(smem + S_OFF_S0);
    float* red = (float*)(smem + S_OFF_RED);   // [64 rows][8 col-warps]

    #pragma unroll
    for (int nb = 0; nb < 4; nb++) {
        float2 sp = *(const float2*)(s0s + wn * 32 + nb * 8 + q * 2);
        #pragma unroll
        for (int mb = 0; mb < 2; mb++) {
            acc[mb][nb][0] += sp.x; acc[mb][nb][1] += sp.y;
            acc[mb][nb][2] += sp.x; acc[mb][nb][3] += sp.y;
        }
    }
    float mx[2][2];
    #pragma unroll
    for (int mb = 0; mb < 2; mb++)
        #pragma unroll
        for (int r = 0; r < 2; r++) {
            float m = -1e30f;
            #pragma unroll
            for (int nb = 0; nb < 4; nb++)
                m = fmaxf(m, fmaxf(acc[mb][nb][r*2], acc[mb][nb][r*2+1]));
            m = fmaxf(m, __shfl_xor_sync(0xffffffffu, m, 1));
            m = fmaxf(m, __shfl_xor_sync(0xffffffffu, m, 2));
            if (q == 0) red[(wm * 32 + mb * 16 + g + r * 8) * 8 + wn] = m;
        }
    __syncthreads();
    #pragma unroll
    for (int mb = 0; mb < 2; mb++)
        #pragma unroll
        for (int r = 0; r < 2; r++) {
            int row = wm * 32 + mb * 16 + g + r * 8;
            float4 r0 = *(const float4*)(red + row * 8);
            float4 r1 = *(const float4*)(red + row * 8 + 4);
            mx[mb][r] = fmaxf(fmaxf(fmaxf(r0.x, r0.y), fmaxf(r0.z, r0.w)),
                              fmaxf(fmaxf(r1.x, r1.y), fmaxf(r1.z, r1.w)));
        }
    __syncthreads();
    #pragma unroll
    for (int mb = 0; mb < 2; mb++)
        #pragma unroll
        for (int r = 0; r < 2; r++) {
            float s = 0.f;
            #pragma unroll
            for (int nb = 0; nb < 4; nb++) {
                float e0 = __expf(acc[mb][nb][r*2]   - mx[mb][r]);
                float e1 = __expf(acc[mb][nb][r*2+1] - mx[mb][r]);
                acc[mb][nb][r*2] = e0; acc[mb][nb][r*2+1] = e1;
                s += e0 + e1;
            }
            s += __shfl_xor_sync(0xffffffffu, s, 1);
            s += __shfl_xor_sync(0xffffffffu, s, 2);
            if (q == 0) red[(wm * 32 + mb * 16 + g + r * 8) * 8 + wn] = s;
        }
    __syncthreads();
    #pragma unroll
    for (int mb = 0; mb < 2; mb++)
        #pragma unroll
        for (int r = 0; r < 2; r++) {
            int row = wm * 32 + mb * 16 + g + r * 8;
            float4 r0 = *(const float4*)(red + row * 8);
            float4 r1 = *(const float4*)(red + row * 8 + 4);
            float inv = 1.f / ((r0.x + r0.y + r0.z + r0.w) + (r1.x + r1.y + r1.z + r1.w));
            size_t grow = (size_t)(row0 + row);
            #pragma unroll
            for (int nb = 0; nb < 4; nb++) {
                float2 o;
                o.x = to_tf32(acc[mb][nb][r*2]   * inv);
                o.y = to_tf32(acc[mb][nb][r*2+1] * inv);
                *(float2*)(g_w + grow * MSLOTS + wn * 32 + nb * 8 + q * 2) = o;
            }
        }
}

// ---------------------------------------------------------------------------
// out = w @ Rt^T + bo + x: CTA = 128 rows x 128 cols, K=256, mma.sync tf32.
// 512 threads = 16 warps in 4x4 grid, warp tile 32x32.
// ---------------------------------------------------------------------------
#define O_AST (128 * LDK * 4)         // 10240
#define O_BST (128 * LDK * 4)         // 10240
#define O_ST  (O_AST + O_BST)         // 20480
#define O_SMEM (4 * O_ST)             // 81920

__global__ __launch_bounds__(512, 1) void out_tc(
    const float* __restrict__ x, const float* __restrict__ bo,
    float* __restrict__ out)
{
    extern __shared__ char smem[];
    const uint32_t sb = smem_u32(smem);
    const int tid = threadIdx.x;
    const int lane = tid & 31, wid = tid >> 5;
    const int wm = wid >> 2, wn = wid & 3;       // warp grid 4x4
    const int g = lane >> 2, q = lane & 3;
    const int row0 = blockIdx.y * 128;
    const int col0 = blockIdx.x * 128;

    auto load_stage = [&](int buf, int kb) {
        uint32_t ab = sb + buf * O_ST;
        uint32_t bb = ab + O_AST;
        {   // A: g_w[row0..+127, kb..kb+15] -- 512 cp16
            int r = tid >> 2, t = tid & 3;
            cp16(ab + (r * LDK + t * 4) * 4, g_w + (size_t)(row0 + r) * MSLOTS + kb + t * 4);
        }
        {   // B: g_Rt[col0..+127, kb..kb+15]
            int r = tid >> 2, t = tid & 3;
            cp16(bb + (r * LDK + t * 4) * 4, g_Rt + (size_t)(col0 + r) * MSLOTS + kb + t * 4);
        }
    };

    float acc[2][4][4] = {};
    #pragma unroll
    for (int p = 0; p < 3; p++) { load_stage(p, p * 16); CP_COMMIT(); }

    for (int s = 0; s < 16; s++) {
        CP_WAIT(2);
        __syncthreads();
        if (s + 3 < 16) load_stage((s + 3) & 3, (s + 3) * 16);
        CP_COMMIT();

        uint32_t aB = sb + (s & 3) * O_ST;
        uint32_t bB = aB + O_AST;
        #pragma unroll
        for (int k8 = 0; k8 < 16; k8 += 8) {
            uint32_t af[2][4], bf[4][2];
            #pragma unroll
            for (int mb = 0; mb < 2; mb++) {
                int row = wm * 32 + mb * 16 + ((lane >> 3) & 1) * 8 + (lane & 7);
                int kof = k8 + ((lane >> 4) << 2);
                LDSM4(af[mb][0], af[mb][1], af[mb][2], af[mb][3],
                      aB + (row * LDK + kof) * 4);
            }
            #pragma unroll
            for (int nb2 = 0; nb2 < 2; nb2++) {
                int n = wn * 32 + nb2 * 16 + ((lane >> 4) & 1) * 8 + (lane & 7);
                int kof = k8 + ((lane >> 3) & 1) * 4;
                LDSM4(bf[nb2*2][0], bf[nb2*2][1], bf[nb2*2+1][0], bf[nb2*2+1][1],
                      bB + (n * LDK + kof) * 4);
            }
            // both operands pre-rounded to tf32 -> no cvt needed
            #pragma unroll
            for (int mb = 0; mb < 2; mb++)
                #pragma unroll
                for (int nb = 0; nb < 4; nb++)
                    MMA_TF32(acc[mb][nb], af[mb], bf[nb]);
        }
    }

    // ---- epilogue: + bo + x ----
    #pragma unroll
    for (int mb = 0; mb < 2; mb++)
        #pragma unroll
        for (int r = 0; r < 2; r++) {
            size_t row = (size_t)(row0 + wm * 32 + mb * 16 + g + r * 8);
            #pragma unroll
            for (int nb = 0; nb < 4; nb++) {
                int col = col0 + wn * 32 + nb * 8 + q * 2;
                float2 xv = *(const float2*)(x + row * EDIM + col);
                float2 bv = *(const float2*)(bo + col);
                float2 o;
                o.x = acc[mb][nb][r*2]   + bv.x + xv.x;
                o.y = acc[mb][nb][r*2+1] + bv.y + xv.y;
                *(float2*)(out + row * EDIM + col) = o;
            }
        }
}

// ---------------------------------------------------------------------------
// Launch
// ---------------------------------------------------------------------------
extern "C" void kernel_launch(void* const* d_in, const int* in_sizes, int n_in,
                              void* d_out, int out_size)
{
    (void)in_sizes; (void)n_in; (void)out_size;
    const float* x  = (const float*)d_in[0];
    const float* Mb = (const float*)d_in[1];
    const float* Wq = (const float*)d_in[2];
    const float* bq = (const float*)d_in[3];
    const float* Wo = (const float*)d_in[4];
    const float* bo = (const float*)d_in[5];
    float* out = (float*)d_out;

    cudaFuncSetAttribute(scores_tc, cudaFuncAttributeMaxDynamicSharedMemorySize, S_SMEM);
    cudaFuncSetAttribute(out_tc,    cudaFuncAttributeMaxDynamicSharedMemorySize, O_SMEM);

    precompute_kernel<<<dim3(EDIM / 64, MSLOTS / 64, 2), 256>>>(Mb, Wq, Wo);
    s0_kernel<<<MSLOTS, 32>>>(Mb, bq);
    scores_tc<<<NROWS / 64, 512, S_SMEM>>>(x);
    out_tc<<<dim3(EDIM / 128, NROWS / 128), 512, O_SMEM>>>(x, bo, out);
}

// round 6
// speedup vs baseline: 2.9391x; 1.0686x over previous
#include <cuda_runtime.h>
#include <cstdint>

#define EDIM   1024
#define MSLOTS 256
#define NROWS  32768

// Scratch (no allocations -> __device__ globals). Values pre-rounded to tf32.
__device__ float g_P [MSLOTS * EDIM];              // P  = M @ Wq       [slot, e]
__device__ float g_Rt[EDIM * MSLOTS];              // Rt = (M @ Wo^T)^T [e, slot]
__device__ float g_s0[MSLOTS];                     // s0 = M @ bq  (full fp32)
__device__ float g_w [(size_t)NROWS * MSLOTS];     // softmax weights   [row, slot]

// ---------------------------------------------------------------------------
// Helpers
// ---------------------------------------------------------------------------
__device__ __forceinline__ uint32_t smem_u32(const void* p) {
    uint32_t a;
    asm("{ .reg .u64 t; cvta.to.shared.u64 t, %1; cvt.u32.u64 %0, t; }" : "=r"(a) : "l"(p));
    return a;
}
__device__ __forceinline__ void cp16(uint32_t dst, const void* src) {
    asm volatile("cp.async.cg.shared.global [%0], [%1], 16;" :: "r"(dst), "l"(src));
}
#define CP_COMMIT() asm volatile("cp.async.commit_group;" ::: "memory")
#define CP_WAIT(n)  asm volatile("cp.async.wait_group %0;" :: "n"(n) : "memory")

#define LDSM4(r0, r1, r2, r3, addr) \
    asm volatile("ldmatrix.sync.aligned.m8n8.x4.shared.b16 {%0,%1,%2,%3}, [%4];" \
        : "=r"(r0), "=r"(r1), "=r"(r2), "=r"(r3) : "r"(addr))

#define MMA_TF32(c, a, b) \
    asm volatile("mma.sync.aligned.m16n8k8.row.col.f32.tf32.tf32.f32 " \
        "{%0,%1,%2,%3}, {%4,%5,%6,%7}, {%8,%9}, {%0,%1,%2,%3};" \
        : "+f"((c)[0]), "+f"((c)[1]), "+f"((c)[2]), "+f"((c)[3]) \
        : "r"((a)[0]), "r"((a)[1]), "r"((a)[2]), "r"((a)[3]), "r"((b)[0]), "r"((b)[1]))

__device__ __forceinline__ float to_tf32(float v) {
    uint32_t u;
    asm("cvt.rna.tf32.f32 %0, %1;" : "=r"(u) : "f"(v));
    return __uint_as_float(u);
}
__device__ __forceinline__ void cvt_tf32_r(uint32_t& u) {
    asm("cvt.rna.tf32.f32 %0, %0;" : "+r"(u));
}

// Padded K stride (floats): 16 + 4 -> 80B rows, conflict-free ldmatrix
#define LDK 20

// ---------------------------------------------------------------------------
// Precompute P (mode 0) and Rt (mode 1), tf32-rounded outputs
// ---------------------------------------------------------------------------
__global__ __launch_bounds__(256) void precompute_kernel(
    const float* __restrict__ Mb, const float* __restrict__ Wq,
    const float* __restrict__ Wo)
{
    constexpr int BM = 64, BN = 64, BK = 32;
    __shared__ float As[BK][BM];
    __shared__ float Bs[BK][BN];
    const int mode = blockIdx.z;
    const int m0 = blockIdx.y * BM;
    const int n0 = blockIdx.x * BN;
    const int tid = threadIdx.x;
    const int tm = tid >> 4, tn = tid & 15;
    float acc[4][4] = {};

    for (int kb = 0; kb < EDIM; kb += BK) {
        {
            int r = tid >> 2, k0 = (tid & 3) * 8;
            float4 v0 = *(const float4*)(Mb + (m0 + r) * EDIM + kb + k0);
            float4 v1 = *(const float4*)(Mb + (m0 + r) * EDIM + kb + k0 + 4);
            As[k0+0][r] = v0.x; As[k0+1][r] = v0.y; As[k0+2][r] = v0.z; As[k0+3][r] = v0.w;
            As[k0+4][r] = v1.x; As[k0+5][r] = v1.y; As[k0+6][r] = v1.z; As[k0+7][r] = v1.w;
        }
        if (mode == 0) {
            int k = tid >> 3, nq = (tid & 7) * 8;
            float4 v0 = *(const float4*)(Wq + (size_t)(kb + k) * EDIM + n0 + nq);
            float4 v1 = *(const float4*)(Wq + (size_t)(kb + k) * EDIM + n0 + nq + 4);
            *(float4*)&Bs[k][nq]     = v0;
            *(float4*)&Bs[k][nq + 4] = v1;
        } else {
            int n = tid >> 2, k0 = (tid & 3) * 8;
            float4 v0 = *(const float4*)(Wo + (size_t)(n0 + n) * EDIM + kb + k0);
            float4 v1 = *(const float4*)(Wo + (size_t)(n0 + n) * EDIM + kb + k0 + 4);
            Bs[k0+0][n] = v0.x; Bs[k0+1][n] = v0.y; Bs[k0+2][n] = v0.z; Bs[k0+3][n] = v0.w;
            Bs[k0+4][n] = v1.x; Bs[k0+5][n] = v1.y; Bs[k0+6][n] = v1.z; Bs[k0+7][n] = v1.w;
        }
        __syncthreads();
        #pragma unroll
        for (int k = 0; k < BK; k++) {
            float a[4], b[4];
            *(float4*)a = *(const float4*)&As[k][tm * 4];
            *(float4*)b = *(const float4*)&Bs[k][tn * 4];
            #pragma unroll
            for (int i = 0; i < 4; i++)
                #pragma unroll
                for (int j = 0; j < 4; j++)
                    acc[i][j] = fmaf(a[i], b[j], acc[i][j]);
        }
        __syncthreads();
    }
    if (mode == 0) {
        #pragma unroll
        for (int i = 0; i < 4; i++) {
            int m = m0 + tm * 4 + i;
            *(float4*)(g_P + (size_t)m * EDIM + n0 + tn * 4) =
                make_float4(to_tf32(acc[i][0]), to_tf32(acc[i][1]),
                            to_tf32(acc[i][2]), to_tf32(acc[i][3]));
        }
    } else {
        #pragma unroll
        for (int i = 0; i < 4; i++)
            #pragma unroll
            for (int j = 0; j < 4; j++)
                g_Rt[(size_t)(n0 + tn * 4 + j) * MSLOTS + (m0 + tm * 4 + i)] = to_tf32(acc[i][j]);
    }
}

__global__ void s0_kernel(const float* __restrict__ Mb, const float* __restrict__ bq)
{
    int m = blockIdx.x;
    int lane = threadIdx.x;
    float s = 0.f;
    #pragma unroll
    for (int c = 0; c < 8; c++) {
        int e = lane * 4 + c * 128;
        float4 mv = *(const float4*)(Mb + (size_t)m * EDIM + e);
        float4 bv = *(const float4*)(bq + e);
        s += mv.x * bv.x + mv.y * bv.y + mv.z * bv.z + mv.w * bv.w;
    }
    #pragma unroll
    for (int o = 16; o; o >>= 1) s += __shfl_xor_sync(0xffffffffu, s, o);
    if (lane == 0) g_s0[m] = s;
}

// ---------------------------------------------------------------------------
// scores + softmax: CTA = 128 rows x 256 slots, K=1024, mma.sync tf32.
// 512 threads = 16 warps in 2x8 grid, warp tile 64x32.
// ---------------------------------------------------------------------------
#define S_AST (128 * LDK * 4)         // 10240
#define S_BST (256 * LDK * 4)         // 20480
#define S_ST  (S_AST + S_BST)         // 30720
#define S_OFF_S0  0                   // 1KB
#define S_OFF_RED 1024                // 128 rows x 8 col-warps x 4B = 4KB
#define S_OFF_STG 5120
#define S_SMEM (S_OFF_STG + 4 * S_ST) // 128000

__global__ __launch_bounds__(512, 1) void scores_tc(const float* __restrict__ x)
{
    extern __shared__ char smem[];
    const uint32_t sb = smem_u32(smem);
    const int tid = threadIdx.x;
    const int lane = tid & 31, wid = tid >> 5;
    const int wm = wid >> 3, wn = wid & 7;       // warp grid 2x8
    const int g = lane >> 2, q = lane & 3;
    const int row0 = blockIdx.x * 128;

    if (tid < 64) ((float4*)(smem + S_OFF_S0))[tid] = ((const float4*)g_s0)[tid];

    auto load_stage = [&](int buf, int kb) {
        uint32_t ab = sb + S_OFF_STG + buf * S_ST;
        uint32_t bb = ab + S_AST;
        {   // A: x[row0..row0+127, kb..kb+15] -- 512 cp16
            int r = tid >> 2, t = tid & 3;
            cp16(ab + (r * LDK + t * 4) * 4, x + (size_t)(row0 + r) * EDIM + kb + t * 4);
        }
        #pragma unroll
        for (int i = 0; i < 2; i++) {   // B: g_P[0..255, kb..kb+15]
            int idx = tid + i * 512;
            int r = idx >> 2, t = idx & 3;
            cp16(bb + (r * LDK + t * 4) * 4, g_P + (size_t)r * EDIM + kb + t * 4);
        }
    };

    float acc[4][4][4] = {};
    #pragma unroll
    for (int p = 0; p < 3; p++) { load_stage(p, p * 16); CP_COMMIT(); }

    for (int s = 0; s < 64; s++) {
        CP_WAIT(2);
        __syncthreads();
        if (s + 3 < 64) load_stage((s + 3) & 3, (s + 3) * 16);
        CP_COMMIT();

        uint32_t aB = sb + S_OFF_STG + (s & 3) * S_ST;
        uint32_t bB = aB + S_AST;
        #pragma unroll
        for (int k8 = 0; k8 < 16; k8 += 8) {
            uint32_t af[4][4], bf[4][2];
            #pragma unroll
            for (int mb = 0; mb < 4; mb++) {
                int row = wm * 64 + mb * 16 + ((lane >> 3) & 1) * 8 + (lane & 7);
                int kof = k8 + ((lane >> 4) << 2);
                LDSM4(af[mb][0], af[mb][1], af[mb][2], af[mb][3],
                      aB + (row * LDK + kof) * 4);
            }
            #pragma unroll
            for (int nb2 = 0; nb2 < 2; nb2++) {
                int n = wn * 32 + nb2 * 16 + ((lane >> 4) & 1) * 8 + (lane & 7);
                int kof = k8 + ((lane >> 3) & 1) * 4;
                LDSM4(bf[nb2*2][0], bf[nb2*2][1], bf[nb2*2+1][0], bf[nb2*2+1][1],
                      bB + (n * LDK + kof) * 4);
            }
            // x is raw fp32 -> round A frags to tf32 (B already rounded)
            #pragma unroll
            for (int mb = 0; mb < 4; mb++)
                #pragma unroll
                for (int i = 0; i < 4; i++) cvt_tf32_r(af[mb][i]);
            #pragma unroll
            for (int mb = 0; mb < 4; mb++)
                #pragma unroll
                for (int nb = 0; nb < 4; nb++)
                    MMA_TF32(acc[mb][nb], af[mb], bf[nb]);
        }
    }

    // ---- softmax epilogue ----
    const float* s0s = (const float*)(smem + S_OFF_S0);
    float* red = (float*)(smem + S_OFF_RED);   // [128 rows][8 col-warps]

    #pragma unroll
    for (int nb = 0; nb < 4; nb++) {
        float2 sp = *(const float2*)(s0s + wn * 32 + nb * 8 + q * 2);
        #pragma unroll
        for (int mb = 0; mb < 4; mb++) {
            acc[mb][nb][0] += sp.x; acc[mb][nb][1] += sp.y;
            acc[mb][nb][2] += sp.x; acc[mb][nb][3] += sp.y;
        }
    }
    float mx[4][2];
    #pragma unroll
    for (int mb = 0; mb < 4; mb++)
        #pragma unroll
        for (int r = 0; r < 2; r++) {
            float m = -1e30f;
            #pragma unroll
            for (int nb = 0; nb < 4; nb++)
                m = fmaxf(m, fmaxf(acc[mb][nb][r*2], acc[mb][nb][r*2+1]));
            m = fmaxf(m, __shfl_xor_sync(0xffffffffu, m, 1));
            m = fmaxf(m, __shfl_xor_sync(0xffffffffu, m, 2));
            if (q == 0) red[(wm * 64 + mb * 16 + g + r * 8) * 8 + wn] = m;
        }
    __syncthreads();
    #pragma unroll
    for (int mb = 0; mb < 4; mb++)
        #pragma unroll
        for (int r = 0; r < 2; r++) {
            int row = wm * 64 + mb * 16 + g + r * 8;
            float4 r0 = *(const float4*)(red + row * 8);
            float4 r1 = *(const float4*)(red + row * 8 + 4);
            mx[mb][r] = fmaxf(fmaxf(fmaxf(r0.x, r0.y), fmaxf(r0.z, r0.w)),
                              fmaxf(fmaxf(r1.x, r1.y), fmaxf(r1.z, r1.w)));
        }
    __syncthreads();
    #pragma unroll
    for (int mb = 0; mb < 4; mb++)
        #pragma unroll
        for (int r = 0; r < 2; r++) {
            float s = 0.f;
            #pragma unroll
            for (int nb = 0; nb < 4; nb++) {
                float e0 = __expf(acc[mb][nb][r*2]   - mx[mb][r]);
                float e1 = __expf(acc[mb][nb][r*2+1] - mx[mb][r]);
                acc[mb][nb][r*2] = e0; acc[mb][nb][r*2+1] = e1;
                s += e0 + e1;
            }
            s += __shfl_xor_sync(0xffffffffu, s, 1);
            s += __shfl_xor_sync(0xffffffffu, s, 2);
            if (q == 0) red[(wm * 64 + mb * 16 + g + r * 8) * 8 + wn] = s;
        }
    __syncthreads();
    #pragma unroll
    for (int mb = 0; mb < 4; mb++)
        #pragma unroll
        for (int r = 0; r < 2; r++) {
            int row = wm * 64 + mb * 16 + g + r * 8;
            float4 r0 = *(const float4*)(red + row * 8);
            float4 r1 = *(const float4*)(red + row * 8 + 4);
            float inv = 1.f / ((r0.x + r0.y + r0.z + r0.w) + (r1.x + r1.y + r1.z + r1.w));
            size_t grow = (size_t)(row0 + row);
            #pragma unroll
            for (int nb = 0; nb < 4; nb++) {
                float2 o;
                o.x = to_tf32(acc[mb][nb][r*2]   * inv);
                o.y = to_tf32(acc[mb][nb][r*2+1] * inv);
                *(float2*)(g_w + grow * MSLOTS + wn * 32 + nb * 8 + q * 2) = o;
            }
        }
}

// ---------------------------------------------------------------------------
// out = w @ Rt^T + bo + x: CTA = 128 rows x 256 cols, K=256, mma.sync tf32.
// 512 threads = 16 warps in 2x8 grid, warp tile 64x32.
// ---------------------------------------------------------------------------
#define O_AST (128 * LDK * 4)         // 10240
#define O_BST (256 * LDK * 4)         // 20480
#define O_ST  (O_AST + O_BST)         // 30720
#define O_SMEM (4 * O_ST)             // 122880

__global__ __launch_bounds__(512, 1) void out_tc(
    const float* __restrict__ x, const float* __restrict__ bo,
    float* __restrict__ out)
{
    extern __shared__ char smem[];
    const uint32_t sb = smem_u32(smem);
    const int tid = threadIdx.x;
    const int lane = tid & 31, wid = tid >> 5;
    const int wm = wid >> 3, wn = wid & 7;       // warp grid 2x8
    const int g = lane >> 2, q = lane & 3;
    const int row0 = blockIdx.y * 128;
    const int col0 = blockIdx.x * 256;

    auto load_stage = [&](int buf, int kb) {
        uint32_t ab = sb + buf * O_ST;
        uint32_t bb = ab + O_AST;
        {   // A: g_w[row0..+127, kb..kb+15] -- 512 cp16
            int r = tid >> 2, t = tid & 3;
            cp16(ab + (r * LDK + t * 4) * 4, g_w + (size_t)(row0 + r) * MSLOTS + kb + t * 4);
        }
        #pragma unroll
        for (int i = 0; i < 2; i++) {   // B: g_Rt[col0..+255, kb..kb+15]
            int idx = tid + i * 512;
            int r = idx >> 2, t = idx & 3;
            cp16(bb + (r * LDK + t * 4) * 4, g_Rt + (size_t)(col0 + r) * MSLOTS + kb + t * 4);
        }
    };

    float acc[4][4][4] = {};
    #pragma unroll
    for (int p = 0; p < 3; p++) { load_stage(p, p * 16); CP_COMMIT(); }

    for (int s = 0; s < 16; s++) {
        CP_WAIT(2);
        __syncthreads();
        if (s + 3 < 16) load_stage((s + 3) & 3, (s + 3) * 16);
        CP_COMMIT();

        uint32_t aB = sb + (s & 3) * O_ST;
        uint32_t bB = aB + O_AST;
        #pragma unroll
        for (int k8 = 0; k8 < 16; k8 += 8) {
            uint32_t af[4][4], bf[4][2];
            #pragma unroll
            for (int mb = 0; mb < 4; mb++) {
                int row = wm * 64 + mb * 16 + ((lane >> 3) & 1) * 8 + (lane & 7);
                int kof = k8 + ((lane >> 4) << 2);
                LDSM4(af[mb][0], af[mb][1], af[mb][2], af[mb][3],
                      aB + (row * LDK + kof) * 4);
            }
            #pragma unroll
            for (int nb2 = 0; nb2 < 2; nb2++) {
                int n = wn * 32 + nb2 * 16 + ((lane >> 4) & 1) * 8 + (lane & 7);
                int kof = k8 + ((lane >> 3) & 1) * 4;
                LDSM4(bf[nb2*2][0], bf[nb2*2][1], bf[nb2*2+1][0], bf[nb2*2+1][1],
                      bB + (n * LDK + kof) * 4);
            }
            // both operands pre-rounded to tf32 -> no cvt needed
            #pragma unroll
            for (int mb = 0; mb < 4; mb++)
                #pragma unroll
                for (int nb = 0; nb < 4; nb++)
                    MMA_TF32(acc[mb][nb], af[mb], bf[nb]);
        }
    }

    // ---- epilogue: + bo + x ----
    #pragma unroll
    for (int mb = 0; mb < 4; mb++)
        #pragma unroll
        for (int r = 0; r < 2; r++) {
            size_t row = (size_t)(row0 + wm * 64 + mb * 16 + g + r * 8);
            #pragma unroll
            for (int nb = 0; nb < 4; nb++) {
                int col = col0 + wn * 32 + nb * 8 + q * 2;
                float2 xv = *(const float2*)(x + row * EDIM + col);
                float2 bv = *(const float2*)(bo + col);
                float2 o;
                o.x = acc[mb][nb][r*2]   + bv.x + xv.x;
                o.y = acc[mb][nb][r*2+1] + bv.y + xv.y;
                *(float2*)(out + row * EDIM + col) = o;
            }
        }
}

// ---------------------------------------------------------------------------
// Launch
// ---------------------------------------------------------------------------
extern "C" void kernel_launch(void* const* d_in, const int* in_sizes, int n_in,
                              void* d_out, int out_size)
{
    (void)in_sizes; (void)n_in; (void)out_size;
    const float* x  = (const float*)d_in[0];
    const float* Mb = (const float*)d_in[1];
    const float* Wq = (const float*)d_in[2];
    const float* bq = (const float*)d_in[3];
    const float* Wo = (const float*)d_in[4];
    const float* bo = (const float*)d_in[5];
    float* out = (float*)d_out;

    cudaFuncSetAttribute(scores_tc, cudaFuncAttributeMaxDynamicSharedMemorySize, S_SMEM);
    cudaFuncSetAttribute(out_tc,    cudaFuncAttributeMaxDynamicSharedMemorySize, O_SMEM);

    precompute_kernel<<<dim3(EDIM / 64, MSLOTS / 64, 2), 256>>>(Mb, Wq, Wo);
    s0_kernel<<<MSLOTS, 32>>>(Mb, bq);
    scores_tc<<<NROWS / 128, 512, S_SMEM>>>(x);
    out_tc<<<dim3(EDIM / 256, NROWS / 128), 512, O_SMEM>>>(x, bo, out);
}